// round 7
// baseline (speedup 1.0000x reference)
#include <cuda_runtime.h>
#include <math.h>
#include <stdint.h>

#define BB 16
#define TT 16
#define LL 128
#define XX 256
#define HH 512
#define YY 256
#define RCTA 8
#define TPB 512

__device__ __align__(16) float g_w1[BB * HH * XX];
__device__ __align__(16) float g_w2[BB * HH * HH];
__device__ __align__(16) float g_w3[BB * HH * HH];
__device__ __align__(16) float g_w4[BB * YY * HH];
__device__ __align__(16) float g_b1[BB * HH];
__device__ __align__(16) float g_b2[BB * HH];
__device__ __align__(16) float g_b3[BB * HH];
__device__ __align__(16) float g_w2T[HH * HH];
__device__ __align__(16) float g_w3T[HH * HH];
__device__ __align__(16) float g_w4T[HH * YY];
__device__ __align__(16) float g_h1A[BB * TT * HH];
__device__ __align__(16) float g_h2A[BB * TT * HH];
__device__ __align__(16) float g_h3A[BB * TT * HH];
__device__ __align__(16) float g_hgA[BB * TT * HH];
__device__ __align__(16) float g_dz1A[BB * TT * HH];
__device__ __align__(16) float g_dz2A[BB * TT * HH];
__device__ __align__(16) float g_dz3A[BB * TT * HH];
__device__ __align__(16) float g_dlA[BB * TT * YY];
__device__ __align__(16) float g_xg[BB * TT * TT];
__device__ __align__(16) float g_ea[BB * LL * HH];
__device__ __align__(16) float g_eb[BB * LL * HH];

__device__ __forceinline__ float warp_sum(float v) {
    v += __shfl_xor_sync(0xffffffffu, v, 16);
    v += __shfl_xor_sync(0xffffffffu, v, 8);
    v += __shfl_xor_sync(0xffffffffu, v, 4);
    v += __shfl_xor_sync(0xffffffffu, v, 2);
    v += __shfl_xor_sync(0xffffffffu, v, 1);
    return v;
}

__device__ __forceinline__ void csync() {
    asm volatile("barrier.cluster.arrive.aligned;" ::: "memory");
    asm volatile("barrier.cluster.wait.aligned;" ::: "memory");
}

__device__ __forceinline__ uint32_t s2u(const void* p) {
    return (uint32_t)__cvta_generic_to_shared(p);
}

__device__ __forceinline__ void st_cluster_f2(uint32_t saddr, int rank, float2 v) {
    uint32_t ra;
    unsigned long long u =
        ((unsigned long long)__float_as_uint(v.y) << 32) | __float_as_uint(v.x);
    asm volatile("mapa.shared::cluster.u32 %0, %1, %2;" : "=r"(ra) : "r"(saddr), "r"(rank));
    asm volatile("st.shared::cluster.b64 [%0], %1;" :: "r"(ra), "l"(u) : "memory");
}

// ---------------- pre-passes ----------------
__global__ void __launch_bounds__(256) k_tr(const float* __restrict__ fc2,
                                            const float* __restrict__ fc3,
                                            const float* __restrict__ fc4) {
    __shared__ float tile[32][33];
    int bid = blockIdx.x;
    const float* src;
    float* dst;
    int RS, CS;
    if (bid < 256) { src = fc2; dst = g_w2T; RS = HH; CS = HH; }
    else if (bid < 512) { src = fc3; dst = g_w3T; bid -= 256; RS = HH; CS = HH; }
    else { src = fc4; dst = g_w4T; bid -= 512; RS = YY; CS = HH; }
    int tpr = CS / 32;
    int r0 = (bid / tpr) * 32, c0 = (bid % tpr) * 32;
    int tx = threadIdx.x & 31, ty = threadIdx.x >> 5;
    for (int i = ty; i < 32; i += 8) tile[i][tx] = src[(size_t)(r0 + i) * CS + c0 + tx];
    __syncthreads();
    for (int i = ty; i < 32; i += 8) dst[(size_t)(c0 + i) * RS + r0 + tx] = tile[tx][i];
}

__global__ void __launch_bounds__(256) k_miscA(const float* __restrict__ b1,
                                               const float* __restrict__ b2,
                                               const float* __restrict__ b3) {
    int gt = blockIdx.x * blockDim.x + threadIdx.x;
    int NT = gridDim.x * blockDim.x;
    for (int i = gt; i < BB * HH; i += NT) {
        int k = i & (HH - 1);
        g_b1[i] = b1[k]; g_b2[i] = b2[k]; g_b3[i] = b3[k];
    }
}

__global__ void __launch_bounds__(256) k_miscB(const float* __restrict__ tx) {
    int gt = blockIdx.x * blockDim.x + threadIdx.x;
    int NT = gridDim.x * blockDim.x;
    int gw = gt >> 5, lane = gt & 31;
    for (int d = gw; d < BB * TT * TT; d += NT >> 5) {
        int b = d >> 8, s1 = (d >> 4) & 15, s2 = d & 15;
        const float4* xa = (const float4*)(tx + (size_t)(b * TT + s1) * XX);
        const float4* xb = (const float4*)(tx + (size_t)(b * TT + s2) * XX);
        float4 a = xa[lane], c = xb[lane];
        float acc = a.x * c.x + a.y * c.y + a.z * c.z + a.w * c.w;
        a = xa[lane + 32]; c = xb[lane + 32];
        acc += a.x * c.x + a.y * c.y + a.z * c.z + a.w * c.w;
        acc = warp_sum(acc);
        if (lane == 0) g_xg[d] = acc;
    }
}

// ---------------- train: register-tiled warp matvec ----------------
template <int K, int RPW>
struct MVR {
    float4 w[RPW][K / 128];
    float4 ua, ub;
};

// preload W rows + correction u's (issued BEFORE the cluster barrier)
template <int K, int RPW>
__device__ __forceinline__ MVR<K, RPW> mvl(const float* __restrict__ W, int nb,
                                           const float* __restrict__ uA, int NU,
                                           int b0, int t, int lane) {
    MVR<K, RPW> R;
#pragma unroll
    for (int j = 0; j < RPW; j++)
#pragma unroll
        for (int i = 0; i < K / 128; i++)
            R.w[j][i] = *(const float4*)(W + (size_t)(nb + j) * K + lane * 4 + i * 128);
    R.ua = make_float4(0.f, 0.f, 0.f, 0.f);
    R.ub = R.ua;
    if (lane < t) {
        const float* p0 = uA + (size_t)(b0 * TT + lane) * NU + nb;
        const float* p1 = uA + (size_t)((b0 + 1) * TT + lane) * NU + nb;
        if (RPW == 4) {
            R.ua = *(const float4*)p0;
            R.ub = *(const float4*)p1;
        } else {
            float2 a = *(const float2*)p0, b = *(const float2*)p1;
            R.ua.x = a.x; R.ua.y = a.y;
            R.ub.x = b.x; R.ub.y = b.y;
        }
    }
    return R;
}

// compute: matvec from regs vs smem vector + low-rank corr + full warp reduce
template <int K, int RPW>
__device__ __forceinline__ void mvc(const MVR<K, RPW>& R, const float2* __restrict__ sx,
                                    const float* s_c, int t, int lane, float2* acc) {
#pragma unroll
    for (int j = 0; j < RPW; j++) acc[j] = make_float2(0.f, 0.f);
#pragma unroll
    for (int i = 0; i < K / 128; i++) {
        const float* xb = (const float*)(sx + lane * 4 + i * 128);
        float4 xa = *(const float4*)xb;
        float4 xc = *(const float4*)(xb + 4);
#pragma unroll
        for (int j = 0; j < RPW; j++) {
            float4 w = R.w[j][i];
            acc[j].x = fmaf(w.x, xa.x, acc[j].x); acc[j].y = fmaf(w.x, xa.y, acc[j].y);
            acc[j].x = fmaf(w.y, xa.z, acc[j].x); acc[j].y = fmaf(w.y, xa.w, acc[j].y);
            acc[j].x = fmaf(w.z, xc.x, acc[j].x); acc[j].y = fmaf(w.z, xc.y, acc[j].y);
            acc[j].x = fmaf(w.w, xc.z, acc[j].x); acc[j].y = fmaf(w.w, xc.w, acc[j].y);
        }
    }
    if (lane < t) {
        float2 c = *(const float2*)&s_c[2 * lane];
        const float* ua = (const float*)&R.ua;
        const float* ub = (const float*)&R.ub;
#pragma unroll
        for (int j = 0; j < RPW; j++) {
            acc[j].x = fmaf(-c.x, ua[j], acc[j].x);
            acc[j].y = fmaf(-c.y, ub[j], acc[j].y);
        }
    }
#pragma unroll
    for (int m = 1; m < 32; m <<= 1)
#pragma unroll
        for (int j = 0; j < RPW; j++) {
            acc[j].x += __shfl_xor_sync(0xffffffffu, acc[j].x, m);
            acc[j].y += __shfl_xor_sync(0xffffffffu, acc[j].y, m);
        }
}

__device__ __forceinline__ void sumc(const float (*sp)[32], float* s_c, int tid, float lr) {
    if (tid < 32) {
        float s = 0.f;
#pragma unroll
        for (int rr = 0; rr < RCTA; rr++) s += sp[rr][tid];
        s_c[tid] = lr * s;
    }
    __syncthreads();
}

template <int NPC, int KD>
__device__ __forceinline__ void publish(float2* dst_vec, float* dst_part,
                                        const float2* s_new,
                                        const float* __restrict__ histA,
                                        int b0, int r, int t, int tid) {
    __syncthreads();
    if (tid < NPC) {
        float2 v = s_new[tid];
        uint32_t sa = s2u(&dst_vec[r * NPC + tid]);
#pragma unroll
        for (int rr = 0; rr < RCTA; rr++) st_cluster_f2(sa, rr, v);
    }
    int w = tid >> 5, lane = tid & 31;
    if (w < t) {
        float a0 = 0.f, a1 = 0.f;
#pragma unroll
        for (int ii = 0; ii < NPC / 32; ii++) {
            int i = lane + 32 * ii;
            float2 nv = s_new[i];
            float h0 = histA[(size_t)(b0 * TT + w) * KD + r * NPC + i];
            float h1 = histA[(size_t)((b0 + 1) * TT + w) * KD + r * NPC + i];
            a0 = fmaf(h0, nv.x, a0);
            a1 = fmaf(h1, nv.y, a1);
        }
        a0 = warp_sum(a0); a1 = warp_sum(a1);
        if (lane == 0) {
            uint32_t sa = s2u(&dst_part[r * 32 + 2 * w]);
#pragma unroll
            for (int rr = 0; rr < RCTA; rr++) st_cluster_f2(sa, rr, make_float2(a0, a1));
        }
    }
}

__global__ void __cluster_dims__(RCTA, 1, 1) __launch_bounds__(TPB, 1)
k_train(const float* __restrict__ tx, const float* __restrict__ ty,
        const float* __restrict__ tg,
        const float* __restrict__ fc1, const float* __restrict__ fc2,
        const float* __restrict__ fc3, const float* __restrict__ fc4,
        const float* __restrict__ loglr) {
    __shared__ __align__(16) float2 s_vec[2][HH];
    __shared__ __align__(16) float s_part[2][RCTA][32];
    __shared__ __align__(16) float2 s_new[64];
    __shared__ float s_c[32];
    int tid = threadIdx.x;
    int r = blockIdx.x & (RCTA - 1);
    int b0 = (blockIdx.x / RCTA) * 2;
    int w = tid >> 5, lane = tid & 31;
    int nb4 = r * 64 + w * 4;   // 4-rows-per-warp base (HH-dim phases)
    int nb2 = r * 32 + w * 2;   // 2-rows-per-warp base (fwd4, YY-dim)
    float lr = expf(*loglr);
    float2 acc[4];

    for (int t = 0; t < TT; t++) {
        // ======== fwd1 (buf A local fill; coeffs from gram) ========
        {
            auto R = mvl<XX, 4>(fc1, nb4, g_dz1A, HH, b0, t, lane);
            const float* x0 = tx + (size_t)(b0 * TT + t) * XX;
            const float* x1 = tx + (size_t)((b0 + 1) * TT + t) * XX;
            for (int k = tid; k < XX; k += TPB)
                s_vec[0][k] = make_float2(x0[k], x1[k]);
            if (tid < 32) {
                int s = tid >> 1, bsel = tid & 1;
                s_c[tid] = (s < t) ? lr * g_xg[((b0 + bsel) * TT + s) * TT + t] : 0.f;
            }
            __syncthreads();
            mvc<XX, 4>(R, s_vec[0], s_c, t, lane, acc);
#pragma unroll
            for (int j = 0; j < 4; j++)
                if (lane == j) {
                    int n = nb4 + j;
                    float h0 = fmaxf(acc[j].x + g_b1[b0 * HH + n], 0.f);
                    float h1 = fmaxf(acc[j].y + g_b1[(b0 + 1) * HH + n], 0.f);
                    g_h1A[(size_t)(b0 * TT + t) * HH + n] = h0;
                    g_h1A[(size_t)((b0 + 1) * TT + t) * HH + n] = h1;
                    s_new[w * 4 + j] = make_float2(h0, h1);
                }
            publish<64, HH>(s_vec[1], &s_part[1][0][0], s_new, g_h1A, b0, r, t, tid);
        }
        // ======== fwd2 (buf B) ========
        {
            auto R = mvl<HH, 4>(fc2, nb4, g_dz2A, HH, b0, t, lane);
            csync();
            sumc(s_part[1], s_c, tid, lr);
            mvc<HH, 4>(R, s_vec[1], s_c, t, lane, acc);
#pragma unroll
            for (int j = 0; j < 4; j++)
                if (lane == j) {
                    int n = nb4 + j;
                    float h0 = fmaxf(acc[j].x + g_b2[b0 * HH + n], 0.f);
                    float h1 = fmaxf(acc[j].y + g_b2[(b0 + 1) * HH + n], 0.f);
                    g_h2A[(size_t)(b0 * TT + t) * HH + n] = h0;
                    g_h2A[(size_t)((b0 + 1) * TT + t) * HH + n] = h1;
                    s_new[w * 4 + j] = make_float2(h0, h1);
                }
            publish<64, HH>(s_vec[0], &s_part[0][0][0], s_new, g_h2A, b0, r, t, tid);
        }
        // ======== fwd3 + gate (buf A) ========
        {
            auto R = mvl<HH, 4>(fc3, nb4, g_dz3A, HH, b0, t, lane);
            csync();
            sumc(s_part[0], s_c, tid, lr);
            mvc<HH, 4>(R, s_vec[0], s_c, t, lane, acc);
#pragma unroll
            for (int j = 0; j < 4; j++)
                if (lane == j) {
                    int n = nb4 + j;
                    float h30 = fmaxf(acc[j].x + g_b3[b0 * HH + n], 0.f);
                    float h31 = fmaxf(acc[j].y + g_b3[(b0 + 1) * HH + n], 0.f);
                    g_h3A[(size_t)(b0 * TT + t) * HH + n] = h30;
                    g_h3A[(size_t)((b0 + 1) * TT + t) * HH + n] = h31;
                    float hg0 = h30 * tg[(size_t)(b0 * TT + t) * HH + n];
                    float hg1 = h31 * tg[(size_t)((b0 + 1) * TT + t) * HH + n];
                    g_hgA[(size_t)(b0 * TT + t) * HH + n] = hg0;
                    g_hgA[(size_t)((b0 + 1) * TT + t) * HH + n] = hg1;
                    s_new[w * 4 + j] = make_float2(hg0, hg1);
                }
            publish<64, HH>(s_vec[1], &s_part[1][0][0], s_new, g_hgA, b0, r, t, tid);
        }
        // ======== fwd4 -> dlogit (buf B), 2 rows/warp ========
        {
            auto R = mvl<HH, 2>(fc4, nb2, g_dlA, YY, b0, t, lane);
            csync();
            sumc(s_part[1], s_c, tid, lr);
            mvc<HH, 2>(R, s_vec[1], s_c, t, lane, acc);
#pragma unroll
            for (int j = 0; j < 2; j++)
                if (lane == j) {
                    int n = nb2 + j;
                    float d0 = (2.f / (float)YY) * (acc[j].x - ty[(size_t)(b0 * TT + t) * YY + n]);
                    float d1 = (2.f / (float)YY) * (acc[j].y - ty[(size_t)((b0 + 1) * TT + t) * YY + n]);
                    g_dlA[(size_t)(b0 * TT + t) * YY + n] = d0;
                    g_dlA[(size_t)((b0 + 1) * TT + t) * YY + n] = d1;
                    s_new[w * 2 + j] = make_float2(d0, d1);
                }
            publish<32, YY>(s_vec[0], &s_part[0][0][0], s_new, g_dlA, b0, r, t, tid);
        }
        // ======== bwd4: dhg -> dz3, b3 (buf A) ========
        {
            auto R = mvl<YY, 4>(g_w4T, nb4, g_hgA, HH, b0, t, lane);
            csync();
            sumc(s_part[0], s_c, tid, lr);
            mvc<YY, 4>(R, s_vec[0], s_c, t, lane, acc);
#pragma unroll
            for (int j = 0; j < 4; j++)
                if (lane == j) {
                    int n = nb4 + j;
                    float h30 = g_h3A[(size_t)(b0 * TT + t) * HH + n];
                    float h31 = g_h3A[(size_t)((b0 + 1) * TT + t) * HH + n];
                    float d0 = (h30 > 0.f) ? acc[j].x * tg[(size_t)(b0 * TT + t) * HH + n] : 0.f;
                    float d1 = (h31 > 0.f) ? acc[j].y * tg[(size_t)((b0 + 1) * TT + t) * HH + n] : 0.f;
                    g_dz3A[(size_t)(b0 * TT + t) * HH + n] = d0;
                    g_dz3A[(size_t)((b0 + 1) * TT + t) * HH + n] = d1;
                    g_b3[b0 * HH + n] -= lr * d0;
                    g_b3[(b0 + 1) * HH + n] -= lr * d1;
                    s_new[w * 4 + j] = make_float2(d0, d1);
                }
            publish<64, HH>(s_vec[1], &s_part[1][0][0], s_new, g_dz3A, b0, r, t, tid);
        }
        // ======== bwd3: dh2 -> dz2, b2 (buf B) ========
        {
            auto R = mvl<HH, 4>(g_w3T, nb4, g_h2A, HH, b0, t, lane);
            csync();
            sumc(s_part[1], s_c, tid, lr);
            mvc<HH, 4>(R, s_vec[1], s_c, t, lane, acc);
#pragma unroll
            for (int j = 0; j < 4; j++)
                if (lane == j) {
                    int n = nb4 + j;
                    float h20 = g_h2A[(size_t)(b0 * TT + t) * HH + n];
                    float h21 = g_h2A[(size_t)((b0 + 1) * TT + t) * HH + n];
                    float d0 = (h20 > 0.f) ? acc[j].x : 0.f;
                    float d1 = (h21 > 0.f) ? acc[j].y : 0.f;
                    g_dz2A[(size_t)(b0 * TT + t) * HH + n] = d0;
                    g_dz2A[(size_t)((b0 + 1) * TT + t) * HH + n] = d1;
                    g_b2[b0 * HH + n] -= lr * d0;
                    g_b2[(b0 + 1) * HH + n] -= lr * d1;
                    s_new[w * 4 + j] = make_float2(d0, d1);
                }
            publish<64, HH>(s_vec[0], &s_part[0][0][0], s_new, g_dz2A, b0, r, t, tid);
        }
        // ======== bwd2: dh1 -> dz1, b1 (buf A; no publish/no barrier) ========
        {
            auto R = mvl<HH, 4>(g_w2T, nb4, g_h1A, HH, b0, t, lane);
            csync();
            sumc(s_part[0], s_c, tid, lr);
            mvc<HH, 4>(R, s_vec[0], s_c, t, lane, acc);
#pragma unroll
            for (int j = 0; j < 4; j++)
                if (lane == j) {
                    int n = nb4 + j;
                    float h10 = g_h1A[(size_t)(b0 * TT + t) * HH + n];
                    float h11 = g_h1A[(size_t)((b0 + 1) * TT + t) * HH + n];
                    float d0 = (h10 > 0.f) ? acc[j].x : 0.f;
                    float d1 = (h11 > 0.f) ? acc[j].y : 0.f;
                    g_dz1A[(size_t)(b0 * TT + t) * HH + n] = d0;
                    g_dz1A[(size_t)((b0 + 1) * TT + t) * HH + n] = d1;
                    g_b1[b0 * HH + n] -= lr * d0;
                    g_b1[(b0 + 1) * HH + n] -= lr * d1;
                }
            __syncthreads();  // protect buf A / s_c before fwd1(t+1)
        }
    }
}

// ---------------- materialize: warp-per-row rank-16 --------------------------
__global__ void __launch_bounds__(256) k_material(
    const float* __restrict__ fc1, const float* __restrict__ fc2,
    const float* __restrict__ fc3, const float* __restrict__ fc4,
    const float* __restrict__ tx, const float* __restrict__ loglr) {
    float lr = expf(*loglr);
    int gw = (blockIdx.x * blockDim.x + threadIdx.x) >> 5;
    int lane = threadIdx.x & 31;
    int NW = (gridDim.x * blockDim.x) >> 5;
    for (int row = gw; row < BB * HH; row += NW) {
        int b = row >> 9, n = row & 511;
        float uval = (lane < TT) ? lr * g_dz1A[(size_t)(b * TT + lane) * HH + n] : 0.f;
#pragma unroll
        for (int it = 0; it < 2; it++) {
            int k4 = lane + it * 32;
            float4 acc = ((const float4*)fc1)[n * 64 + k4];
#pragma unroll
            for (int s = 0; s < TT; s++) {
                float u = __shfl_sync(0xffffffffu, uval, s);
                float4 v = ((const float4*)tx)[(b * TT + s) * 64 + k4];
                acc.x -= u * v.x; acc.y -= u * v.y; acc.z -= u * v.z; acc.w -= u * v.w;
            }
            ((float4*)g_w1)[(size_t)row * 64 + k4] = acc;
        }
    }
    for (int row = gw; row < BB * HH; row += NW) {
        int b = row >> 9, n = row & 511;
        float uval = (lane < TT) ? lr * g_dz2A[(size_t)(b * TT + lane) * HH + n] : 0.f;
#pragma unroll
        for (int it = 0; it < 4; it++) {
            int k4 = lane + it * 32;
            float4 acc = ((const float4*)fc2)[n * 128 + k4];
#pragma unroll
            for (int s = 0; s < TT; s++) {
                float u = __shfl_sync(0xffffffffu, uval, s);
                float4 v = ((const float4*)g_h1A)[(b * TT + s) * 128 + k4];
                acc.x -= u * v.x; acc.y -= u * v.y; acc.z -= u * v.z; acc.w -= u * v.w;
            }
            ((float4*)g_w2)[(size_t)row * 128 + k4] = acc;
        }
    }
    for (int row = gw; row < BB * HH; row += NW) {
        int b = row >> 9, n = row & 511;
        float uval = (lane < TT) ? lr * g_dz3A[(size_t)(b * TT + lane) * HH + n] : 0.f;
#pragma unroll
        for (int it = 0; it < 4; it++) {
            int k4 = lane + it * 32;
            float4 acc = ((const float4*)fc3)[n * 128 + k4];
#pragma unroll
            for (int s = 0; s < TT; s++) {
                float u = __shfl_sync(0xffffffffu, uval, s);
                float4 v = ((const float4*)g_h2A)[(b * TT + s) * 128 + k4];
                acc.x -= u * v.x; acc.y -= u * v.y; acc.z -= u * v.z; acc.w -= u * v.w;
            }
            ((float4*)g_w3)[(size_t)row * 128 + k4] = acc;
        }
    }
    for (int row = gw; row < BB * YY; row += NW) {
        int b = row >> 8, n = row & 255;
        float uval = (lane < TT) ? lr * g_dlA[(size_t)(b * TT + lane) * YY + n] : 0.f;
#pragma unroll
        for (int it = 0; it < 4; it++) {
            int k4 = lane + it * 32;
            float4 acc = ((const float4*)fc4)[n * 128 + k4];
#pragma unroll
            for (int s = 0; s < TT; s++) {
                float u = __shfl_sync(0xffffffffu, uval, s);
                float4 v = ((const float4*)g_hgA)[(b * TT + s) * 128 + k4];
                acc.x -= u * v.x; acc.y -= u * v.y; acc.z -= u * v.z; acc.w -= u * v.w;
            }
            ((float4*)g_w4)[(size_t)row * 128 + k4] = acc;
        }
    }
}

// ---------------- eval: tiled fp32 GEMM -------------------
template <int LAYER>
__global__ void __launch_bounds__(256) k_eval(const float* __restrict__ extin,
                                              const float* __restrict__ gate,
                                              float* __restrict__ outp) {
    constexpr int N = (LAYER == 4) ? YY : HH;
    constexpr int K = (LAYER == 1) ? XX : HH;
    constexpr int NBLK = N / 128;
    __shared__ float Ws[32 * 129];
    __shared__ float Xs[64 * 33];
    int lb = blockIdx.x & 1;
    int tmp = blockIdx.x >> 1;
    int nb = tmp & (NBLK - 1);
    int b = tmp / NBLK;
    const float* W = (LAYER == 1) ? g_w1 : (LAYER == 2) ? g_w2 : (LAYER == 3) ? g_w3 : g_w4;
    const float* in = (LAYER == 1) ? extin : (LAYER == 2) ? g_ea : (LAYER == 3) ? g_eb : g_ea;
    const float* Wb = W + ((size_t)b * N + nb * 128) * K;
    const float* Ib = in + ((size_t)b * LL + lb * 64) * K;
    int tid = threadIdx.x;
    int tc = tid & 31, tr = tid >> 5;
    float acc[8][4];
#pragma unroll
    for (int i = 0; i < 8; i++)
#pragma unroll
        for (int d = 0; d < 4; d++) acc[i][d] = 0.f;
    for (int kc = 0; kc < K; kc += 32) {
#pragma unroll
        for (int s = 0; s < 16; s++) {
            int e = tid + s * 256;
            int kk = e & 31, n = e >> 5;
            Ws[kk * 129 + n] = Wb[(size_t)n * K + kc + kk];
        }
#pragma unroll
        for (int s = 0; s < 8; s++) {
            int e = tid + s * 256;
            int kk = e & 31, l = e >> 5;
            Xs[l * 33 + kk] = Ib[(size_t)l * K + kc + kk];
        }
        __syncthreads();
#pragma unroll
        for (int kk = 0; kk < 32; kk++) {
            float w0 = Ws[kk * 129 + tc];
            float w1 = Ws[kk * 129 + tc + 32];
            float w2 = Ws[kk * 129 + tc + 64];
            float w3 = Ws[kk * 129 + tc + 96];
#pragma unroll
            for (int i = 0; i < 8; i++) {
                float xv = Xs[(tr * 8 + i) * 33 + kk];
                acc[i][0] = fmaf(xv, w0, acc[i][0]);
                acc[i][1] = fmaf(xv, w1, acc[i][1]);
                acc[i][2] = fmaf(xv, w2, acc[i][2]);
                acc[i][3] = fmaf(xv, w3, acc[i][3]);
            }
        }
        __syncthreads();
    }
    float bv[4] = {0.f, 0.f, 0.f, 0.f};
    if (LAYER != 4) {
        const float* bias = (LAYER == 1) ? g_b1 : (LAYER == 2) ? g_b2 : g_b3;
#pragma unroll
        for (int d = 0; d < 4; d++) bv[d] = bias[b * HH + nb * 128 + tc + 32 * d];
    }
    float* op = (LAYER == 4) ? outp : (LAYER == 1) ? g_ea : (LAYER == 2) ? g_eb : g_ea;
#pragma unroll
    for (int i = 0; i < 8; i++) {
        int l = lb * 64 + tr * 8 + i;
        size_t rowo = ((size_t)b * LL + l) * N + nb * 128;
#pragma unroll
        for (int d = 0; d < 4; d++) {
            float v = acc[i][d];
            if (LAYER != 4) v = fmaxf(v + bv[d], 0.f);
            if (LAYER == 3) v *= gate[((size_t)b * LL + l) * HH + nb * 128 + tc + 32 * d];
            op[rowo + tc + 32 * d] = v;
        }
    }
}

__global__ void k_loss(const float* __restrict__ ty, const float* __restrict__ loglr,
                       float* __restrict__ out) {
    int gw = (blockIdx.x * blockDim.x + threadIdx.x) >> 5;
    int lane = threadIdx.x & 31;
    if (gw >= BB * LL) return;
    const float* lg = out + 4097 + (size_t)gw * YY;
    const float* tyv = ty + (size_t)gw * YY;
    float acc = 0.f;
#pragma unroll
    for (int k = lane, it = 0; it < YY / 32; it++, k += 32) {
        float d = lg[k] - tyv[k];
        acc = fmaf(d, d, acc);
    }
    acc = warp_sum(acc);
    if (lane == 0) {
        float m = acc * (1.f / (float)YY);
        out[gw] = m;
        out[2049 + gw] = m;
    }
    if (gw == 0 && lane == 0) out[2048] = expf(*loglr);
}

extern "C" void kernel_launch(void* const* d_in, const int* in_sizes, int n_in,
                              void* d_out, int out_size) {
    const float* train_x = (const float*)d_in[0];
    const float* train_y = (const float*)d_in[1];
    const float* test_x = (const float*)d_in[2];
    const float* test_y = (const float*)d_in[3];
    const float* train_gate = (const float*)d_in[4];
    const float* test_gate = (const float*)d_in[5];
    const float* fc1 = (const float*)d_in[6];
    const float* b1 = (const float*)d_in[7];
    const float* fc2 = (const float*)d_in[8];
    const float* b2 = (const float*)d_in[9];
    const float* fc3 = (const float*)d_in[10];
    const float* b3 = (const float*)d_in[11];
    const float* fc4 = (const float*)d_in[12];
    const float* loglr = (const float*)d_in[13];
    float* out = (float*)d_out;

    k_tr<<<640, 256>>>(fc2, fc3, fc4);
    k_miscA<<<32, 256>>>(b1, b2, b3);
    k_miscB<<<64, 256>>>(train_x);
    k_train<<<64, TPB>>>(train_x, train_y, train_gate, fc1, fc2, fc3, fc4, loglr);
    k_material<<<1024, 256>>>(fc1, fc2, fc3, fc4, train_x, loglr);

    k_eval<1><<<BB * (HH / 128) * 2, 256>>>(test_x, nullptr, nullptr);
    k_eval<2><<<BB * (HH / 128) * 2, 256>>>(nullptr, nullptr, nullptr);
    k_eval<3><<<BB * (HH / 128) * 2, 256>>>(nullptr, test_gate, nullptr);
    k_eval<4><<<BB * (YY / 128) * 2, 256>>>(nullptr, nullptr, out + 4097);

    k_loss<<<256, 256>>>(test_y, loglr, out);
}

// round 8
// speedup vs baseline: 1.0578x; 1.0578x over previous
#include <cuda_runtime.h>
#include <math.h>
#include <stdint.h>

#define BB 16
#define TT 16
#define LL 128
#define XX 256
#define HH 512
#define YY 256
#define RCTA 8
#define TPB 512

__device__ __align__(16) float g_w1[BB * HH * XX];
__device__ __align__(16) float g_w2[BB * HH * HH];
__device__ __align__(16) float g_w3[BB * HH * HH];
__device__ __align__(16) float g_w4[BB * YY * HH];
__device__ __align__(16) float g_b1[BB * HH];
__device__ __align__(16) float g_b2[BB * HH];
__device__ __align__(16) float g_b3[BB * HH];
__device__ __align__(16) float g_w2T[HH * HH];
__device__ __align__(16) float g_w3T[HH * HH];
__device__ __align__(16) float g_w4T[HH * YY];
__device__ __align__(16) float g_h1A[BB * TT * HH];
__device__ __align__(16) float g_h2A[BB * TT * HH];
__device__ __align__(16) float g_h3A[BB * TT * HH];
__device__ __align__(16) float g_hgA[BB * TT * HH];
__device__ __align__(16) float g_dz1A[BB * TT * HH];
__device__ __align__(16) float g_dz2A[BB * TT * HH];
__device__ __align__(16) float g_dz3A[BB * TT * HH];
__device__ __align__(16) float g_dlA[BB * TT * YY];
__device__ __align__(16) float g_xg[BB * TT * TT];
__device__ __align__(16) float g_ea[BB * LL * HH];
__device__ __align__(16) float g_eb[BB * LL * HH];

__device__ __forceinline__ float warp_sum(float v) {
    v += __shfl_xor_sync(0xffffffffu, v, 16);
    v += __shfl_xor_sync(0xffffffffu, v, 8);
    v += __shfl_xor_sync(0xffffffffu, v, 4);
    v += __shfl_xor_sync(0xffffffffu, v, 2);
    v += __shfl_xor_sync(0xffffffffu, v, 1);
    return v;
}

__device__ __forceinline__ void csync() {
    asm volatile("barrier.cluster.arrive.aligned;" ::: "memory");
    asm volatile("barrier.cluster.wait.aligned;" ::: "memory");
}

__device__ __forceinline__ uint32_t s2u(const void* p) {
    return (uint32_t)__cvta_generic_to_shared(p);
}

__device__ __forceinline__ void st_cluster_f2(uint32_t saddr, int rank, float2 v) {
    uint32_t ra;
    unsigned long long u =
        ((unsigned long long)__float_as_uint(v.y) << 32) | __float_as_uint(v.x);
    asm volatile("mapa.shared::cluster.u32 %0, %1, %2;" : "=r"(ra) : "r"(saddr), "r"(rank));
    asm volatile("st.shared::cluster.b64 [%0], %1;" :: "r"(ra), "l"(u) : "memory");
}

// packed fp32x2 helpers (true FFMA2, no per-op packing)
__device__ __forceinline__ void ffma2l(unsigned long long& d, unsigned long long a,
                                       unsigned long long b) {
    asm("fma.rn.f32x2 %0, %1, %2, %0;" : "+l"(d) : "l"(a), "l"(b));
}
__device__ __forceinline__ unsigned long long splat2(float w) {
    unsigned long long r;
    asm("mov.b64 %0, {%1, %1};" : "=l"(r) : "f"(w));
    return r;
}
__device__ __forceinline__ float2 unpk(unsigned long long v) {
    float2 r;
    asm("mov.b64 {%0, %1}, %2;" : "=f"(r.x), "=f"(r.y) : "l"(v));
    return r;
}

// ---------------- pre-passes ----------------
__global__ void __launch_bounds__(256) k_tr(const float* __restrict__ fc2,
                                            const float* __restrict__ fc3,
                                            const float* __restrict__ fc4) {
    __shared__ float tile[32][33];
    int bid = blockIdx.x;
    const float* src;
    float* dst;
    int RS, CS;
    if (bid < 256) { src = fc2; dst = g_w2T; RS = HH; CS = HH; }
    else if (bid < 512) { src = fc3; dst = g_w3T; bid -= 256; RS = HH; CS = HH; }
    else { src = fc4; dst = g_w4T; bid -= 512; RS = YY; CS = HH; }
    int tpr = CS / 32;
    int r0 = (bid / tpr) * 32, c0 = (bid % tpr) * 32;
    int tx = threadIdx.x & 31, ty = threadIdx.x >> 5;
    for (int i = ty; i < 32; i += 8) tile[i][tx] = src[(size_t)(r0 + i) * CS + c0 + tx];
    __syncthreads();
    for (int i = ty; i < 32; i += 8) dst[(size_t)(c0 + i) * RS + r0 + tx] = tile[tx][i];
}

__global__ void __launch_bounds__(256) k_miscA(const float* __restrict__ b1,
                                               const float* __restrict__ b2,
                                               const float* __restrict__ b3) {
    int gt = blockIdx.x * blockDim.x + threadIdx.x;
    int NT = gridDim.x * blockDim.x;
    for (int i = gt; i < BB * HH; i += NT) {
        int k = i & (HH - 1);
        g_b1[i] = b1[k]; g_b2[i] = b2[k]; g_b3[i] = b3[k];
    }
}

__global__ void __launch_bounds__(256) k_miscB(const float* __restrict__ tx) {
    int gt = blockIdx.x * blockDim.x + threadIdx.x;
    int NT = gridDim.x * blockDim.x;
    int gw = gt >> 5, lane = gt & 31;
    for (int d = gw; d < BB * TT * TT; d += NT >> 5) {
        int b = d >> 8, s1 = (d >> 4) & 15, s2 = d & 15;
        const float4* xa = (const float4*)(tx + (size_t)(b * TT + s1) * XX);
        const float4* xb = (const float4*)(tx + (size_t)(b * TT + s2) * XX);
        float4 a = xa[lane], c = xb[lane];
        float acc = a.x * c.x + a.y * c.y + a.z * c.z + a.w * c.w;
        a = xa[lane + 32]; c = xb[lane + 32];
        acc += a.x * c.x + a.y * c.y + a.z * c.z + a.w * c.w;
        acc = warp_sum(acc);
        if (lane == 0) g_xg[d] = acc;
    }
}

// ---------------- train building blocks (R6 proven version) ----------------
template <int K>
__device__ __forceinline__ float2 omv_s(const float* __restrict__ W, int n,
                                        const float2* __restrict__ sv, int l8) {
    const float4* w4 = (const float4*)(W + (size_t)n * K);
    const float4* v4 = (const float4*)sv;
    float a0 = 0.f, a1 = 0.f, c0 = 0.f, c1 = 0.f;
#pragma unroll
    for (int jj = 0; jj < K / 32; jj++) {
        int j = l8 + jj * 8;
        float4 w = w4[j];
        float4 p = v4[2 * j], q = v4[2 * j + 1];
        a0 = fmaf(w.x, p.x, a0); a1 = fmaf(w.x, p.y, a1);
        c0 = fmaf(w.y, p.z, c0); c1 = fmaf(w.y, p.w, c1);
        a0 = fmaf(w.z, q.x, a0); a1 = fmaf(w.z, q.y, a1);
        c0 = fmaf(w.w, q.z, c0); c1 = fmaf(w.w, q.w, c1);
    }
    return make_float2(a0 + c0, a1 + c1);
}

__device__ __forceinline__ void ored2(float2& a) {
#pragma unroll
    for (int m = 1; m < 8; m <<= 1) {
        a.x += __shfl_xor_sync(0xffffffffu, a.x, m);
        a.y += __shfl_xor_sync(0xffffffffu, a.y, m);
    }
}

template <int NU>
__device__ __forceinline__ void corr2(const float* __restrict__ uA, int b0, int n,
                                      const float* s_c, int t, int l8, float2& a) {
#pragma unroll
    for (int ss = 0; ss < 2; ss++) {
        int s = l8 + ss * 8;
        if (s < t) {
            float u0 = uA[(size_t)(b0 * TT + s) * NU + n];
            float u1 = uA[(size_t)((b0 + 1) * TT + s) * NU + n];
            a.x = fmaf(-s_c[2 * s], u0, a.x);
            a.y = fmaf(-s_c[2 * s + 1], u1, a.y);
        }
    }
}

__device__ __forceinline__ void sumc(const float (*sp)[32], float* s_c, int tid, float lr) {
    if (tid < 32) {
        float s = 0.f;
#pragma unroll
        for (int rr = 0; rr < RCTA; rr++) s += sp[rr][tid];
        s_c[tid] = lr * s;
    }
    __syncthreads();
}

template <int NPC, int KD>
__device__ __forceinline__ void publish(float2* dst_vec, float* dst_part,
                                        const float2* s_new,
                                        const float* __restrict__ histA,
                                        int b0, int r, int t, int tid) {
    __syncthreads();
    if (tid < NPC) {
        float2 v = s_new[tid];
        uint32_t sa = s2u(&dst_vec[r * NPC + tid]);
#pragma unroll
        for (int rr = 0; rr < RCTA; rr++) st_cluster_f2(sa, rr, v);
    }
    int w = tid >> 5, lane = tid & 31;
    if (w < t) {
        float a0 = 0.f, a1 = 0.f;
#pragma unroll
        for (int ii = 0; ii < NPC / 32; ii++) {
            int i = lane + 32 * ii;
            float2 nv = s_new[i];
            float h0 = histA[(size_t)(b0 * TT + w) * KD + r * NPC + i];
            float h1 = histA[(size_t)((b0 + 1) * TT + w) * KD + r * NPC + i];
            a0 = fmaf(h0, nv.x, a0);
            a1 = fmaf(h1, nv.y, a1);
        }
        a0 = warp_sum(a0); a1 = warp_sum(a1);
        if (lane == 0) {
            uint32_t sa = s2u(&dst_part[r * 32 + 2 * w]);
#pragma unroll
            for (int rr = 0; rr < RCTA; rr++) st_cluster_f2(sa, rr, make_float2(a0, a1));
        }
    }
}

__global__ void __cluster_dims__(RCTA, 1, 1) __launch_bounds__(TPB, 1)
k_train(const float* __restrict__ tx, const float* __restrict__ ty,
        const float* __restrict__ tg,
        const float* __restrict__ fc1, const float* __restrict__ fc2,
        const float* __restrict__ fc3, const float* __restrict__ fc4,
        const float* __restrict__ loglr) {
    __shared__ __align__(16) float2 s_vec[2][HH];
    __shared__ __align__(16) float s_part[2][RCTA][32];
    __shared__ __align__(16) float2 s_new[64];
    __shared__ float s_c[32];
    int tid = threadIdx.x;
    int r = blockIdx.x & (RCTA - 1);
    int b0 = (blockIdx.x / RCTA) * 2;
    int l8 = tid & 7;
    int oct = tid >> 3;
    float lr = expf(*loglr);

    for (int t = 0; t < TT; t++) {
        // ======== fwd1 ========
        {
            const float* x0 = tx + (size_t)(b0 * TT + t) * XX;
            const float* x1 = tx + (size_t)((b0 + 1) * TT + t) * XX;
            for (int k = tid; k < XX; k += TPB)
                s_vec[0][k] = make_float2(x0[k], x1[k]);
            if (tid < 32) {
                int s = tid >> 1, bsel = tid & 1;
                s_c[tid] = (s < t) ? lr * g_xg[((b0 + bsel) * TT + s) * TT + t] : 0.f;
            }
            __syncthreads();
            int n = r * 64 + oct;
            float2 a = omv_s<XX>(fc1, n, s_vec[0], l8);
            corr2<HH>(g_dz1A, b0, n, s_c, t, l8, a);
            ored2(a);
            if (l8 == 0) {
                float h0 = fmaxf(a.x + g_b1[b0 * HH + n], 0.f);
                float h1 = fmaxf(a.y + g_b1[(b0 + 1) * HH + n], 0.f);
                g_h1A[(size_t)(b0 * TT + t) * HH + n] = h0;
                g_h1A[(size_t)((b0 + 1) * TT + t) * HH + n] = h1;
                s_new[oct] = make_float2(h0, h1);
            }
            publish<64, HH>(s_vec[1], &s_part[1][0][0], s_new, g_h1A, b0, r, t, tid);
            csync();
        }
        // ======== fwd2 ========
        {
            sumc(s_part[1], s_c, tid, lr);
            int n = r * 64 + oct;
            float2 a = omv_s<HH>(fc2, n, s_vec[1], l8);
            corr2<HH>(g_dz2A, b0, n, s_c, t, l8, a);
            ored2(a);
            if (l8 == 0) {
                float h0 = fmaxf(a.x + g_b2[b0 * HH + n], 0.f);
                float h1 = fmaxf(a.y + g_b2[(b0 + 1) * HH + n], 0.f);
                g_h2A[(size_t)(b0 * TT + t) * HH + n] = h0;
                g_h2A[(size_t)((b0 + 1) * TT + t) * HH + n] = h1;
                s_new[oct] = make_float2(h0, h1);
            }
            publish<64, HH>(s_vec[0], &s_part[0][0][0], s_new, g_h2A, b0, r, t, tid);
            csync();
        }
        // ======== fwd3 + gate ========
        {
            sumc(s_part[0], s_c, tid, lr);
            int n = r * 64 + oct;
            float2 a = omv_s<HH>(fc3, n, s_vec[0], l8);
            corr2<HH>(g_dz3A, b0, n, s_c, t, l8, a);
            ored2(a);
            if (l8 == 0) {
                float h30 = fmaxf(a.x + g_b3[b0 * HH + n], 0.f);
                float h31 = fmaxf(a.y + g_b3[(b0 + 1) * HH + n], 0.f);
                g_h3A[(size_t)(b0 * TT + t) * HH + n] = h30;
                g_h3A[(size_t)((b0 + 1) * TT + t) * HH + n] = h31;
                float hg0 = h30 * tg[(size_t)(b0 * TT + t) * HH + n];
                float hg1 = h31 * tg[(size_t)((b0 + 1) * TT + t) * HH + n];
                g_hgA[(size_t)(b0 * TT + t) * HH + n] = hg0;
                g_hgA[(size_t)((b0 + 1) * TT + t) * HH + n] = hg1;
                s_new[oct] = make_float2(hg0, hg1);
            }
            publish<64, HH>(s_vec[1], &s_part[1][0][0], s_new, g_hgA, b0, r, t, tid);
            csync();
        }
        // ======== fwd4 -> dlogit ========
        {
            sumc(s_part[1], s_c, tid, lr);
            if (oct < 32) {
                int n = r * 32 + oct;
                float2 a = omv_s<HH>(fc4, n, s_vec[1], l8);
                corr2<YY>(g_dlA, b0, n, s_c, t, l8, a);
                ored2(a);
                if (l8 == 0) {
                    float d0 = (2.f / (float)YY) * (a.x - ty[(size_t)(b0 * TT + t) * YY + n]);
                    float d1 = (2.f / (float)YY) * (a.y - ty[(size_t)((b0 + 1) * TT + t) * YY + n]);
                    g_dlA[(size_t)(b0 * TT + t) * YY + n] = d0;
                    g_dlA[(size_t)((b0 + 1) * TT + t) * YY + n] = d1;
                    s_new[oct] = make_float2(d0, d1);
                }
            }
            publish<32, YY>(s_vec[0], &s_part[0][0][0], s_new, g_dlA, b0, r, t, tid);
            csync();
        }
        // ======== bwd4 ========
        {
            sumc(s_part[0], s_c, tid, lr);
            int n = r * 64 + oct;
            float2 a = omv_s<YY>(g_w4T, n, s_vec[0], l8);
            corr2<HH>(g_hgA, b0, n, s_c, t, l8, a);
            ored2(a);
            if (l8 == 0) {
                float h30 = g_h3A[(size_t)(b0 * TT + t) * HH + n];
                float h31 = g_h3A[(size_t)((b0 + 1) * TT + t) * HH + n];
                float d0 = (h30 > 0.f) ? a.x * tg[(size_t)(b0 * TT + t) * HH + n] : 0.f;
                float d1 = (h31 > 0.f) ? a.y * tg[(size_t)((b0 + 1) * TT + t) * HH + n] : 0.f;
                g_dz3A[(size_t)(b0 * TT + t) * HH + n] = d0;
                g_dz3A[(size_t)((b0 + 1) * TT + t) * HH + n] = d1;
                g_b3[b0 * HH + n] -= lr * d0;
                g_b3[(b0 + 1) * HH + n] -= lr * d1;
                s_new[oct] = make_float2(d0, d1);
            }
            publish<64, HH>(s_vec[1], &s_part[1][0][0], s_new, g_dz3A, b0, r, t, tid);
            csync();
        }
        // ======== bwd3 ========
        {
            sumc(s_part[1], s_c, tid, lr);
            int n = r * 64 + oct;
            float2 a = omv_s<HH>(g_w3T, n, s_vec[1], l8);
            corr2<HH>(g_h2A, b0, n, s_c, t, l8, a);
            ored2(a);
            if (l8 == 0) {
                float h20 = g_h2A[(size_t)(b0 * TT + t) * HH + n];
                float h21 = g_h2A[(size_t)((b0 + 1) * TT + t) * HH + n];
                float d0 = (h20 > 0.f) ? a.x : 0.f;
                float d1 = (h21 > 0.f) ? a.y : 0.f;
                g_dz2A[(size_t)(b0 * TT + t) * HH + n] = d0;
                g_dz2A[(size_t)((b0 + 1) * TT + t) * HH + n] = d1;
                g_b2[b0 * HH + n] -= lr * d0;
                g_b2[(b0 + 1) * HH + n] -= lr * d1;
                s_new[oct] = make_float2(d0, d1);
            }
            publish<64, HH>(s_vec[0], &s_part[0][0][0], s_new, g_dz2A, b0, r, t, tid);
            csync();
        }
        // ======== bwd2 ========
        {
            sumc(s_part[0], s_c, tid, lr);
            int n = r * 64 + oct;
            float2 a = omv_s<HH>(g_w2T, n, s_vec[0], l8);
            corr2<HH>(g_h1A, b0, n, s_c, t, l8, a);
            ored2(a);
            if (l8 == 0) {
                float h10 = g_h1A[(size_t)(b0 * TT + t) * HH + n];
                float h11 = g_h1A[(size_t)((b0 + 1) * TT + t) * HH + n];
                float d0 = (h10 > 0.f) ? a.x : 0.f;
                float d1 = (h11 > 0.f) ? a.y : 0.f;
                g_dz1A[(size_t)(b0 * TT + t) * HH + n] = d0;
                g_dz1A[(size_t)((b0 + 1) * TT + t) * HH + n] = d1;
                g_b1[b0 * HH + n] -= lr * d0;
                g_b1[(b0 + 1) * HH + n] -= lr * d1;
            }
            __syncthreads();
        }
    }
}

// ---------------- materialize: warp-per-row rank-16 --------------------------
__global__ void __launch_bounds__(256) k_material(
    const float* __restrict__ fc1, const float* __restrict__ fc2,
    const float* __restrict__ fc3, const float* __restrict__ fc4,
    const float* __restrict__ tx, const float* __restrict__ loglr) {
    float lr = expf(*loglr);
    int gw = (blockIdx.x * blockDim.x + threadIdx.x) >> 5;
    int lane = threadIdx.x & 31;
    int NW = (gridDim.x * blockDim.x) >> 5;
    for (int row = gw; row < BB * HH; row += NW) {
        int b = row >> 9, n = row & 511;
        float uval = (lane < TT) ? lr * g_dz1A[(size_t)(b * TT + lane) * HH + n] : 0.f;
#pragma unroll
        for (int it = 0; it < 2; it++) {
            int k4 = lane + it * 32;
            float4 acc = ((const float4*)fc1)[n * 64 + k4];
#pragma unroll
            for (int s = 0; s < TT; s++) {
                float u = __shfl_sync(0xffffffffu, uval, s);
                float4 v = ((const float4*)tx)[(b * TT + s) * 64 + k4];
                acc.x -= u * v.x; acc.y -= u * v.y; acc.z -= u * v.z; acc.w -= u * v.w;
            }
            ((float4*)g_w1)[(size_t)row * 64 + k4] = acc;
        }
    }
    for (int row = gw; row < BB * HH; row += NW) {
        int b = row >> 9, n = row & 511;
        float uval = (lane < TT) ? lr * g_dz2A[(size_t)(b * TT + lane) * HH + n] : 0.f;
#pragma unroll
        for (int it = 0; it < 4; it++) {
            int k4 = lane + it * 32;
            float4 acc = ((const float4*)fc2)[n * 128 + k4];
#pragma unroll
            for (int s = 0; s < TT; s++) {
                float u = __shfl_sync(0xffffffffu, uval, s);
                float4 v = ((const float4*)g_h1A)[(b * TT + s) * 128 + k4];
                acc.x -= u * v.x; acc.y -= u * v.y; acc.z -= u * v.z; acc.w -= u * v.w;
            }
            ((float4*)g_w2)[(size_t)row * 128 + k4] = acc;
        }
    }
    for (int row = gw; row < BB * HH; row += NW) {
        int b = row >> 9, n = row & 511;
        float uval = (lane < TT) ? lr * g_dz3A[(size_t)(b * TT + lane) * HH + n] : 0.f;
#pragma unroll
        for (int it = 0; it < 4; it++) {
            int k4 = lane + it * 32;
            float4 acc = ((const float4*)fc3)[n * 128 + k4];
#pragma unroll
            for (int s = 0; s < TT; s++) {
                float u = __shfl_sync(0xffffffffu, uval, s);
                float4 v = ((const float4*)g_h2A)[(b * TT + s) * 128 + k4];
                acc.x -= u * v.x; acc.y -= u * v.y; acc.z -= u * v.z; acc.w -= u * v.w;
            }
            ((float4*)g_w3)[(size_t)row * 128 + k4] = acc;
        }
    }
    for (int row = gw; row < BB * YY; row += NW) {
        int b = row >> 8, n = row & 255;
        float uval = (lane < TT) ? lr * g_dlA[(size_t)(b * TT + lane) * YY + n] : 0.f;
#pragma unroll
        for (int it = 0; it < 4; it++) {
            int k4 = lane + it * 32;
            float4 acc = ((const float4*)fc4)[n * 128 + k4];
#pragma unroll
            for (int s = 0; s < TT; s++) {
                float u = __shfl_sync(0xffffffffu, uval, s);
                float4 v = ((const float4*)g_hgA)[(b * TT + s) * 128 + k4];
                acc.x -= u * v.x; acc.y -= u * v.y; acc.z -= u * v.z; acc.w -= u * v.w;
            }
            ((float4*)g_w4)[(size_t)row * 128 + k4] = acc;
        }
    }
}

// ---------------- eval: tiled GEMM, true packed FFMA2 ------------------------
template <int LAYER>
__global__ void __launch_bounds__(256) k_eval(const float* __restrict__ extin,
                                              const float* __restrict__ gate,
                                              float* __restrict__ outp) {
    constexpr int N = (LAYER == 4) ? YY : HH;
    constexpr int K = (LAYER == 1) ? XX : HH;
    constexpr int NBLK = N / 128;
    __shared__ float Ws[32 * 129];
    __shared__ float Xs[32 * 66];   // kk-major: Xs[kk*66 + l], l in [0,64)
    int lb = blockIdx.x & 1;
    int tmp = blockIdx.x >> 1;
    int nb = tmp & (NBLK - 1);
    int b = tmp / NBLK;
    const float* W = (LAYER == 1) ? g_w1 : (LAYER == 2) ? g_w2 : (LAYER == 3) ? g_w3 : g_w4;
    const float* in = (LAYER == 1) ? extin : (LAYER == 2) ? g_ea : (LAYER == 3) ? g_eb : g_ea;
    const float* Wb = W + ((size_t)b * N + nb * 128) * K;
    const float* Ib = in + ((size_t)b * LL + lb * 64) * K;
    int tid = threadIdx.x;
    int tc = tid & 31, tr = tid >> 5;
    unsigned long long acc[4][4];   // [l-pair][n-col]
#pragma unroll
    for (int i = 0; i < 4; i++)
#pragma unroll
        for (int d = 0; d < 4; d++) acc[i][d] = 0ull;
    for (int kc = 0; kc < K; kc += 32) {
#pragma unroll
        for (int s = 0; s < 16; s++) {
            int e = tid + s * 256;
            int kk = e & 31, n = e >> 5;
            Ws[kk * 129 + n] = Wb[(size_t)n * K + kc + kk];
        }
#pragma unroll
        for (int s = 0; s < 8; s++) {
            int e = tid + s * 256;
            int kk = e & 31, l = e >> 5;
            Xs[kk * 66 + l] = Ib[(size_t)l * K + kc + kk];
        }
        __syncthreads();
#pragma unroll
        for (int kk = 0; kk < 32; kk++) {
            unsigned long long s0 = splat2(Ws[kk * 129 + tc]);
            unsigned long long s1 = splat2(Ws[kk * 129 + tc + 32]);
            unsigned long long s2 = splat2(Ws[kk * 129 + tc + 64]);
            unsigned long long s3 = splat2(Ws[kk * 129 + tc + 96]);
#pragma unroll
            for (int ip = 0; ip < 4; ip++) {
                unsigned long long xp =
                    *(const unsigned long long*)&Xs[kk * 66 + tr * 8 + 2 * ip];
                ffma2l(acc[ip][0], xp, s0);
                ffma2l(acc[ip][1], xp, s1);
                ffma2l(acc[ip][2], xp, s2);
                ffma2l(acc[ip][3], xp, s3);
            }
        }
        __syncthreads();
    }
    float bv[4] = {0.f, 0.f, 0.f, 0.f};
    if (LAYER != 4) {
        const float* bias = (LAYER == 1) ? g_b1 : (LAYER == 2) ? g_b2 : g_b3;
#pragma unroll
        for (int d = 0; d < 4; d++) bv[d] = bias[b * HH + nb * 128 + tc + 32 * d];
    }
    float* op = (LAYER == 4) ? outp : (LAYER == 1) ? g_ea : (LAYER == 2) ? g_eb : g_ea;
#pragma unroll
    for (int ip = 0; ip < 4; ip++) {
#pragma unroll
        for (int h = 0; h < 2; h++) {
            int l = lb * 64 + tr * 8 + 2 * ip + h;
            size_t rowo = ((size_t)b * LL + l) * N + nb * 128;
#pragma unroll
            for (int d = 0; d < 4; d++) {
                float2 pr = unpk(acc[ip][d]);
                float v = h ? pr.y : pr.x;
                if (LAYER != 4) v = fmaxf(v + bv[d], 0.f);
                if (LAYER == 3)
                    v *= gate[((size_t)b * LL + l) * HH + nb * 128 + tc + 32 * d];
                op[rowo + tc + 32 * d] = v;
            }
        }
    }
}

__global__ void k_loss(const float* __restrict__ ty, const float* __restrict__ loglr,
                       float* __restrict__ out) {
    int gw = (blockIdx.x * blockDim.x + threadIdx.x) >> 5;
    int lane = threadIdx.x & 31;
    if (gw >= BB * LL) return;
    const float* lg = out + 4097 + (size_t)gw * YY;
    const float* tyv = ty + (size_t)gw * YY;
    float acc = 0.f;
#pragma unroll
    for (int k = lane, it = 0; it < YY / 32; it++, k += 32) {
        float d = lg[k] - tyv[k];
        acc = fmaf(d, d, acc);
    }
    acc = warp_sum(acc);
    if (lane == 0) {
        float m = acc * (1.f / (float)YY);
        out[gw] = m;
        out[2049 + gw] = m;
    }
    if (gw == 0 && lane == 0) out[2048] = expf(*loglr);
}

extern "C" void kernel_launch(void* const* d_in, const int* in_sizes, int n_in,
                              void* d_out, int out_size) {
    const float* train_x = (const float*)d_in[0];
    const float* train_y = (const float*)d_in[1];
    const float* test_x = (const float*)d_in[2];
    const float* test_y = (const float*)d_in[3];
    const float* train_gate = (const float*)d_in[4];
    const float* test_gate = (const float*)d_in[5];
    const float* fc1 = (const float*)d_in[6];
    const float* b1 = (const float*)d_in[7];
    const float* fc2 = (const float*)d_in[8];
    const float* b2 = (const float*)d_in[9];
    const float* fc3 = (const float*)d_in[10];
    const float* b3 = (const float*)d_in[11];
    const float* fc4 = (const float*)d_in[12];
    const float* loglr = (const float*)d_in[13];
    float* out = (float*)d_out;

    k_tr<<<640, 256>>>(fc2, fc3, fc4);
    k_miscA<<<32, 256>>>(b1, b2, b3);
    k_miscB<<<64, 256>>>(train_x);
    k_train<<<64, TPB>>>(train_x, train_y, train_gate, fc1, fc2, fc3, fc4, loglr);
    k_material<<<1024, 256>>>(fc1, fc2, fc3, fc4, train_x, loglr);

    k_eval<1><<<BB * (HH / 128) * 2, 256>>>(test_x, nullptr, nullptr);
    k_eval<2><<<BB * (HH / 128) * 2, 256>>>(nullptr, nullptr, nullptr);
    k_eval<3><<<BB * (HH / 128) * 2, 256>>>(nullptr, test_gate, nullptr);
    k_eval<4><<<BB * (YY / 128) * 2, 256>>>(nullptr, nullptr, out + 4097);

    k_loss<<<256, 256>>>(test_y, loglr, out);
}